// round 5
// baseline (speedup 1.0000x reference)
#include <cuda_runtime.h>
#include <math.h>

#define NFFT  2048
#define LOG2N 11
#define TPB   256
#define EPT   (NFFT / TPB)        // 8 elements per thread
#define BPT   (NFFT / 2 / TPB)    // 4 butterflies per thread
#define MAXB  64
#define NS    81                  // number of scales (J=80 -> 81)
#define WSZ   94                  // sliding window = 32*3 - 2
#define NOUT  (NFFT - WSZ + 1)    // 1955

#define PI_F  3.14159265358979323846f
#define TWO_PI_F 6.28318530717958647692f

// ---------------- scratch (static device globals; no runtime alloc) ----------
__device__ float2 g_yh[MAXB * 2 * NFFT];          // forward FFT of normalized inputs
__device__ float  g_T1[MAXB * NS * NFFT];         // smooth(|W1|^2/s)
__device__ float  g_T2[MAXB * NS * NFFT];         // smooth(|W2|^2/s)
__device__ float2 g_T12[MAXB * NS * NFFT];        // smooth(W1*conj(W2)/s)
__device__ float  g_coh[MAXB * NFFT];             // coherence summed over scales

// ---------------- shared-memory Stockham radix-2 FFT, N = 2048 ----------------
// input in sA (caller must __syncthreads() after filling), output in sB
// (11 stages = odd number of ping-pongs). No 1/N scaling applied.
__device__ __noinline__ void fft2048(float2* sA, float2* sB, const float2* __restrict__ tw,
                                     int tid, bool inverse) {
  float2* src = sA;
  float2* dst = sB;
  int mul = 1;
  #pragma unroll
  for (int ls = 0; ls < LOG2N; ++ls) {
    const int s = 1 << ls;
    #pragma unroll
    for (int r = 0; r < BPT; ++r) {
      int t = tid + r * TPB;       // butterfly id in [0, N/2)
      int p = t >> ls;
      int q = t & (s - 1);
      float2 w = tw[p * mul];      // e^{-2*pi*i * (p*mul) / N}
      float wy = inverse ? -w.y : w.y;
      int iu = q + s * p;
      float2 u = src[iu];
      float2 v = src[iu + (NFFT / 2)];
      int io = iu + s * p;
      dst[io] = make_float2(u.x + v.x, u.y + v.y);
      float dx = u.x - v.x, dy = u.y - v.y;
      dst[io + s] = make_float2(dx * w.x - dy * wy, dx * wy + dy * w.x);
    }
    __syncthreads();
    float2* tp = src; src = dst; dst = tp;
    mul <<= 1;
  }
}

__device__ __forceinline__ void build_tw(float2* tw, int tid) {
  #pragma unroll
  for (int r = 0; r < BPT; ++r) {
    int j = tid + r * TPB;
    float sv, cv;
    sincosf(-PI_F * (float)j * (1.0f / 1024.0f), &sv, &cv);
    tw[j] = make_float2(cv, sv);
  }
}

// ---------------- K1: normalize + forward FFT of each input signal ------------
__global__ void kern_fft_input(const float* __restrict__ x) {
  __shared__ float2 sA[NFFT];
  __shared__ float2 sB[NFFT];
  __shared__ float2 tw[NFFT / 2];
  __shared__ float  red[TPB];
  const int bc  = blockIdx.x;   // b*2 + channel
  const int tid = threadIdx.x;

  build_tw(tw, tid);

  const float* y = x + (size_t)bc * NFFT;
  float vals[EPT];
  float sum = 0.f, sumsq = 0.f;
  #pragma unroll
  for (int r = 0; r < EPT; ++r) {
    float v = y[tid + r * TPB];
    vals[r] = v;
    sum += v;
    sumsq += v * v;
  }
  // block reductions
  red[tid] = sum; __syncthreads();
  for (int o = TPB / 2; o > 0; o >>= 1) { if (tid < o) red[tid] += red[tid + o]; __syncthreads(); }
  float mean = red[0] * (1.0f / NFFT);
  __syncthreads();
  red[tid] = sumsq; __syncthreads();
  for (int o = TPB / 2; o > 0; o >>= 1) { if (tid < o) red[tid] += red[tid + o]; __syncthreads(); }
  float var = red[0] * (1.0f / NFFT) - mean * mean;
  float istd = rsqrtf(var);
  __syncthreads();

  #pragma unroll
  for (int r = 0; r < EPT; ++r)
    sA[tid + r * TPB] = make_float2((vals[r] - mean) * istd, 0.f);
  __syncthreads();

  fft2048(sA, sB, tw, tid, false);      // forward FFT, result in sB

  #pragma unroll
  for (int r = 0; r < EPT; ++r) {
    int k = tid + r * TPB;
    g_yh[(size_t)bc * NFFT + k] = sB[k];
  }
}

// ---------------- K2: per (batch, scale) CWT + time smoothing -----------------
__global__ void kern_scale() {
  __shared__ float2 sA[NFFT];
  __shared__ float2 sB[NFFT];
  __shared__ float2 tw[NFFT / 2];
  const int si  = blockIdx.x;   // scale index
  const int b   = blockIdx.y;   // batch
  const int tid = threadIdx.x;

  build_tw(tw, tid);

  // scale value (computed in double to match numpy float64 -> float32 cast)
  const double s0d = 2.0 * 0.1 * (6.0 + sqrt(38.0)) / (4.0 * 3.14159265358979323846);
  const float  sc    = (float)(s0d * exp2(0.125 * (double)si));
  const float  inv_s = 1.0f / sc;
  const float  norm  = sqrtf(TWO_PI_F * sc * 10.0f) * 0.75112554446494248f;  // sqrt(2*pi*s/dt)*pi^-.25
  const float  sdt   = sc * 10.0f;        // s / dt
  const float  INVN  = 1.0f / (float)NFFT;

  float2 w1[EPT], w2[EPT];

  // --- W1, W2: ifft( yh * norm * psi_hat ) ; psi_hat nonzero for k in [1,1023]
  #pragma unroll
  for (int c = 0; c < 2; ++c) {
    #pragma unroll
    for (int r = 0; r < EPT; ++r) {
      int k = tid + r * TPB;
      float2 v = make_float2(0.f, 0.f);
      if (k >= 1 && k < NFFT / 2) {
        float w = TWO_PI_F * (float)k * (1.0f / 204.8f);   // 2*pi*fftfreq(2048, 0.1)
        float d = sc * w - 6.0f;
        float g = norm * expf(-0.5f * d * d);
        float2 yh = g_yh[(size_t)(b * 2 + c) * NFFT + k];
        v = make_float2(yh.x * g, yh.y * g);
      }
      sA[k] = v;
    }
    __syncthreads();
    fft2048(sA, sB, tw, tid, true);
    #pragma unroll
    for (int r = 0; r < EPT; ++r) {
      int k = tid + r * TPB;
      float2 v = sB[k];
      if (c == 0) w1[r] = make_float2(v.x * INVN, v.y * INVN);
      else        w2[r] = make_float2(v.x * INVN, v.y * INVN);
    }
    __syncthreads();
  }

  const size_t base = ((size_t)b * NS + si) * NFFT;

  // --- packed power smoothing: P = |W1|^2/s + i*|W2|^2/s
  // F(k) is real and even => smoothing separates exactly into (T1, T2)
  #pragma unroll
  for (int r = 0; r < EPT; ++r) {
    int k = tid + r * TPB;
    float2 a = w1[r], bb = w2[r];
    sA[k] = make_float2((a.x * a.x + a.y * a.y) * inv_s,
                        (bb.x * bb.x + bb.y * bb.y) * inv_s);
  }
  __syncthreads();
  fft2048(sA, sB, tw, tid, false);
  #pragma unroll
  for (int r = 0; r < EPT; ++r) {
    int k = tid + r * TPB;
    float fk = (float)(k < NFFT / 2 ? k : k - NFFT) * (1.0f / NFFT);
    float kk = TWO_PI_F * fk;
    float F = expf(-0.5f * sdt * sdt * kk * kk);
    float2 v = sB[k];
    sA[k] = make_float2(v.x * F, v.y * F);
  }
  __syncthreads();
  fft2048(sA, sB, tw, tid, true);
  #pragma unroll
  for (int r = 0; r < EPT; ++r) {
    int k = tid + r * TPB;
    float2 v = sB[k];
    g_T1[base + k] = v.x * INVN;
    g_T2[base + k] = v.y * INVN;
  }
  __syncthreads();

  // --- cross spectrum smoothing: C = W1*conj(W2)/s (complex)
  #pragma unroll
  for (int r = 0; r < EPT; ++r) {
    int k = tid + r * TPB;
    float2 a = w1[r], bb = w2[r];
    sA[k] = make_float2((a.x * bb.x + a.y * bb.y) * inv_s,
                        (a.y * bb.x - a.x * bb.y) * inv_s);
  }
  __syncthreads();
  fft2048(sA, sB, tw, tid, false);
  #pragma unroll
  for (int r = 0; r < EPT; ++r) {
    int k = tid + r * TPB;
    float fk = (float)(k < NFFT / 2 ? k : k - NFFT) * (1.0f / NFFT);
    float kk = TWO_PI_F * fk;
    float F = expf(-0.5f * sdt * sdt * kk * kk);
    float2 v = sB[k];
    sA[k] = make_float2(v.x * F, v.y * F);
  }
  __syncthreads();
  fft2048(sA, sB, tw, tid, true);
  #pragma unroll
  for (int r = 0; r < EPT; ++r) {
    int k = tid + r * TPB;
    float2 v = sB[k];
    g_T12[base + k] = make_float2(v.x * INVN, v.y * INVN);
  }
}

// ---------------- K3: scale smoothing + coherence + sum over scales -----------
// jnp.convolve(col, win, 'same'), win = [.5,1,...,1,.5]/9 (len 10):
// S_sm[i] = (1/9) * sum_{j=i-5..i+4, clipped} w(j)*col[j], w = 0.5 at j=i-5, i+4.
// The 1/9 cancels in |S12|^2/(S1*S2), so it is omitted.
__global__ void kern_coh() {
  const int b = blockIdx.y;
  const int t = blockIdx.x * TPB + threadIdx.x;
  const size_t bb = (size_t)b * NS * NFFT + t;
  float acc = 0.f;
  for (int i = 0; i < NS; ++i) {
    float s1 = 0.f, s2 = 0.f, cr = 0.f, ci = 0.f;
    int j0 = i - 5 < 0 ? 0 : i - 5;
    int j1 = i + 4 >= NS ? NS - 1 : i + 4;
    for (int j = j0; j <= j1; ++j) {
      float wgt = (j == i - 5 || j == i + 4) ? 0.5f : 1.0f;
      size_t off = bb + (size_t)j * NFFT;
      s1 += wgt * __ldg(&g_T1[off]);
      s2 += wgt * __ldg(&g_T2[off]);
      float2 c = __ldg(&g_T12[off]);
      cr += wgt * c.x;
      ci += wgt * c.y;
    }
    acc += (cr * cr + ci * ci) / (s1 * s2);
  }
  g_coh[(size_t)b * NFFT + t] = acc;
}

// ---------------- K4: sliding window sum (WSZ=94) ------------------------------
__global__ void kern_slide(float* __restrict__ out) {
  __shared__ float sc[NFFT];
  const int b = blockIdx.x;
  const int tid = threadIdx.x;
  #pragma unroll
  for (int r = 0; r < EPT; ++r)
    sc[tid + r * TPB] = g_coh[(size_t)b * NFFT + tid + r * TPB];
  __syncthreads();
  for (int i = tid; i < NOUT; i += TPB) {
    float s = 0.f;
    for (int k = 0; k < WSZ; ++k) s += sc[i + k];
    out[(size_t)b * NOUT + i] = s;
  }
}

// ---------------- launch -------------------------------------------------------
extern "C" void kernel_launch(void* const* d_in, const int* in_sizes, int n_in,
                              void* d_out, int out_size) {
  const float* x = (const float*)d_in[0];
  int B = in_sizes[0] / (2 * NFFT);
  if (B > MAXB) B = MAXB;
  if (B <= 0) return;

  kern_fft_input<<<B * 2, TPB>>>(x);
  kern_scale<<<dim3(NS, B), TPB>>>();
  kern_coh<<<dim3(NFFT / TPB, B), TPB>>>();
  kern_slide<<<B, TPB>>>((float*)d_out);
}

// round 7
// speedup vs baseline: 1.5582x; 1.5582x over previous
#include <cuda_runtime.h>
#include <math.h>

#define NFFT  2048
#define TPB   256
#define EPT   (NFFT / TPB)        // 8 elements per thread
#define MAXB  64
#define NS    81                  // number of scales (J=80 -> 81)
#define WSZ   94                  // sliding window = 32*3 - 2
#define NOUT  (NFFT - WSZ + 1)    // 1955

#define PI_F  3.14159265358979323846f
#define TWO_PI_F 6.28318530717958647692f

// SMEM padding: 1 extra float2 per 8 -> conflict-free radix-8 exchanges
#define PIDX(i) ((i) + ((i) >> 3))
#define PADN  2304                // PIDX(2047)+1 = 2303, rounded

// ---------------- scratch (static device globals; no runtime alloc) ----------
__device__ float2 g_yh[MAXB * 2 * NFFT];          // forward FFT of normalized inputs
__device__ float  g_T1[MAXB * NS * NFFT];         // smooth(|W1|^2/s)
__device__ float  g_T2[MAXB * NS * NFFT];         // smooth(|W2|^2/s)
__device__ float2 g_T12[MAXB * NS * NFFT];        // smooth(W1*conj(W2)/s)
__device__ float  g_coh[MAXB * NFFT];             // coherence summed over scales

// ---------------- complex helpers ---------------------------------------------
__device__ __forceinline__ float2 cadd(float2 a, float2 b){ return make_float2(a.x+b.x, a.y+b.y); }
__device__ __forceinline__ float2 csub(float2 a, float2 b){ return make_float2(a.x-b.x, a.y-b.y); }
__device__ __forceinline__ float2 cmul(float2 a, float2 b){
  return make_float2(a.x*b.x - a.y*b.y, a.x*b.y + a.y*b.x);
}
// multiply by -i (forward) or +i (inverse)
__device__ __forceinline__ float2 rotm(float2 a, bool inv){
  return inv ? make_float2(-a.y, a.x) : make_float2(a.y, -a.x);
}

// ---------------- radix-8 Stockham stage (S = current span) --------------------
// reads  a_k = src[q + S*p + k*(N/8)];  b_j = radix-8 DFT(a)
// writes dst[q + S*(8p + j)] = b_j * w^j, w = e^{-2*pi*i p S / N}
template<int S>
__device__ __forceinline__ void stage8(const float2* __restrict__ src, float2* __restrict__ dst,
                                       const float2* __restrict__ tw, int tid, bool inv) {
  const int p = tid / S;
  const int q = tid - p * S;
  const int rb = q + S * p;

  float2 a0 = src[PIDX(rb +  256*0)];
  float2 a1 = src[PIDX(rb +  256*1)];
  float2 a2 = src[PIDX(rb +  256*2)];
  float2 a3 = src[PIDX(rb +  256*3)];
  float2 a4 = src[PIDX(rb +  256*4)];
  float2 a5 = src[PIDX(rb +  256*5)];
  float2 a6 = src[PIDX(rb +  256*6)];
  float2 a7 = src[PIDX(rb +  256*7)];

  const float C = 0.70710678118654752440f;
  float2 t0 = cadd(a0,a4), t4 = csub(a0,a4);
  float2 t1 = cadd(a1,a5), t5 = csub(a1,a5);
  float2 t2 = cadd(a2,a6), t6 = csub(a2,a6);
  float2 t3 = cadd(a3,a7), t7 = csub(a3,a7);

  const float2 w81 = inv ? make_float2(C,  C) : make_float2(C, -C);
  const float2 w83 = inv ? make_float2(-C, C) : make_float2(-C,-C);
  t5 = cmul(t5, w81);
  t6 = rotm(t6, inv);
  t7 = cmul(t7, w83);

  float2 u0 = cadd(t0,t2), u2 = csub(t0,t2);
  float2 u1 = cadd(t1,t3), u3 = rotm(csub(t1,t3), inv);
  float2 b0 = cadd(u0,u1), b4 = csub(u0,u1);
  float2 b2 = cadd(u2,u3), b6 = csub(u2,u3);

  float2 v0 = cadd(t4,t6), v2 = csub(t4,t6);
  float2 v1 = cadd(t5,t7), v3 = rotm(csub(t5,t7), inv);
  float2 b1 = cadd(v0,v1), b5 = csub(v0,v1);
  float2 b3 = cadd(v2,v3), b7 = csub(v2,v3);

  float2 w1 = tw[p * S];
  if (inv) w1.y = -w1.y;
  float2 w2 = cmul(w1, w1);
  float2 w3 = cmul(w2, w1);
  float2 w4 = cmul(w2, w2);
  float2 w5 = cmul(w3, w2);
  float2 w6 = cmul(w3, w3);
  float2 w7 = cmul(w4, w3);

  const int wb = q + S * 8 * p;
  dst[PIDX(wb + 0*S)] = b0;
  dst[PIDX(wb + 1*S)] = cmul(b1, w1);
  dst[PIDX(wb + 2*S)] = cmul(b2, w2);
  dst[PIDX(wb + 3*S)] = cmul(b3, w3);
  dst[PIDX(wb + 4*S)] = cmul(b4, w4);
  dst[PIDX(wb + 5*S)] = cmul(b5, w5);
  dst[PIDX(wb + 6*S)] = cmul(b6, w6);
  dst[PIDX(wb + 7*S)] = cmul(b7, w7);
}

// final radix-4 stage: S=512, p=0 -> trivial twiddles
__device__ __forceinline__ void stage4f(const float2* __restrict__ src, float2* __restrict__ dst,
                                        int tid, bool inv) {
  #pragma unroll
  for (int r = 0; r < 2; ++r) {
    const int q = tid + r * TPB;
    float2 a0 = src[PIDX(q)];
    float2 a1 = src[PIDX(q +  512)];
    float2 a2 = src[PIDX(q + 1024)];
    float2 a3 = src[PIDX(q + 1536)];
    float2 t0 = cadd(a0,a2), t1 = csub(a0,a2);
    float2 t2 = cadd(a1,a3), t3 = rotm(csub(a1,a3), inv);
    dst[PIDX(q)]        = cadd(t0,t2);
    dst[PIDX(q +  512)] = cadd(t1,t3);
    dst[PIDX(q + 1024)] = csub(t0,t2);
    dst[PIDX(q + 1536)] = csub(t1,t3);
  }
}

// N=2048 FFT, 4 stages (8*8*8*4). Caller fills sA (at PIDX) then __syncthreads().
// Result ends in sA. No 1/N scaling.
__device__ __noinline__ void fftr8(float2* sA, float2* sB, const float2* __restrict__ tw,
                                   int tid, bool inv) {
  stage8<1> (sA, sB, tw, tid, inv); __syncthreads();
  stage8<8> (sB, sA, tw, tid, inv); __syncthreads();
  stage8<64>(sA, sB, tw, tid, inv); __syncthreads();
  stage4f   (sB, sA, tid, inv);     __syncthreads();
}

__device__ __forceinline__ void build_tw(float2* tw, int tid) {
  #pragma unroll
  for (int r = 0; r < 4; ++r) {
    int j = tid + r * TPB;
    float sv, cv;
    sincosf(-PI_F * (float)j * (1.0f / 1024.0f), &sv, &cv);
    tw[j] = make_float2(cv, sv);
  }
}

// ---------------- K1: normalize + forward FFT of each input signal ------------
__global__ void kern_fft_input(const float* __restrict__ x) {
  __shared__ float2 sA[PADN];
  __shared__ float2 sB[PADN];
  __shared__ float2 tw[NFFT / 2];
  __shared__ float  red[TPB];
  const int bc  = blockIdx.x;   // b*2 + channel
  const int tid = threadIdx.x;

  build_tw(tw, tid);

  const float* y = x + (size_t)bc * NFFT;
  float vals[EPT];
  float sum = 0.f, sumsq = 0.f;
  #pragma unroll
  for (int r = 0; r < EPT; ++r) {
    float v = y[tid + r * TPB];
    vals[r] = v;
    sum += v;
    sumsq += v * v;
  }
  red[tid] = sum; __syncthreads();
  for (int o = TPB / 2; o > 0; o >>= 1) { if (tid < o) red[tid] += red[tid + o]; __syncthreads(); }
  float mean = red[0] * (1.0f / NFFT);
  __syncthreads();
  red[tid] = sumsq; __syncthreads();
  for (int o = TPB / 2; o > 0; o >>= 1) { if (tid < o) red[tid] += red[tid + o]; __syncthreads(); }
  float var = red[0] * (1.0f / NFFT) - mean * mean;
  float istd = rsqrtf(var);
  __syncthreads();

  #pragma unroll
  for (int r = 0; r < EPT; ++r)
    sA[PIDX(tid + r * TPB)] = make_float2((vals[r] - mean) * istd, 0.f);
  __syncthreads();

  fftr8(sA, sB, tw, tid, false);

  #pragma unroll
  for (int r = 0; r < EPT; ++r) {
    int k = tid + r * TPB;
    g_yh[(size_t)bc * NFFT + k] = sA[PIDX(k)];
  }
}

// ---------------- K2: per (batch, scale) CWT + time smoothing -----------------
__global__ void __launch_bounds__(TPB) kern_scale() {
  __shared__ float2 sA[PADN];
  __shared__ float2 sB[PADN];
  __shared__ float2 tw[NFFT / 2];
  const int si  = blockIdx.x;   // scale index
  const int b   = blockIdx.y;   // batch
  const int tid = threadIdx.x;

  build_tw(tw, tid);

  const double s0d = 2.0 * 0.1 * (6.0 + sqrt(38.0)) / (4.0 * 3.14159265358979323846);
  const float  sc    = (float)(s0d * exp2(0.125 * (double)si));
  const float  inv_s = 1.0f / sc;
  const float  norm  = sqrtf(TWO_PI_F * sc * 10.0f) * 0.75112554446494248f;
  const float  sdt   = sc * 10.0f;
  const float  INVN  = 1.0f / (float)NFFT;

  float2 w1[EPT], w2[EPT];

  // --- W1, W2: ifft( yh * norm * psi_hat ) ; psi_hat nonzero for k in [1,1023]
  #pragma unroll
  for (int c = 0; c < 2; ++c) {
    #pragma unroll
    for (int r = 0; r < EPT; ++r) {
      int k = tid + r * TPB;
      float2 v = make_float2(0.f, 0.f);
      if (k >= 1 && k < NFFT / 2) {
        float w = TWO_PI_F * (float)k * (1.0f / 204.8f);
        float d = sc * w - 6.0f;
        float g = norm * expf(-0.5f * d * d);
        float2 yh = g_yh[(size_t)(b * 2 + c) * NFFT + k];
        v = make_float2(yh.x * g, yh.y * g);
      }
      sA[PIDX(k)] = v;
    }
    __syncthreads();
    fftr8(sA, sB, tw, tid, true);
    #pragma unroll
    for (int r = 0; r < EPT; ++r) {
      float2 v = sA[PIDX(tid + r * TPB)];
      if (c == 0) w1[r] = make_float2(v.x * INVN, v.y * INVN);
      else        w2[r] = make_float2(v.x * INVN, v.y * INVN);
    }
    // no sync needed: each thread rewrites only its own slots next iteration
  }

  const size_t base = ((size_t)b * NS + si) * NFFT;

  // --- packed power smoothing: P = |W1|^2/s + i*|W2|^2/s (filter real-even)
  #pragma unroll
  for (int r = 0; r < EPT; ++r) {
    int k = tid + r * TPB;
    float2 a = w1[r], bb = w2[r];
    sA[PIDX(k)] = make_float2((a.x * a.x + a.y * a.y) * inv_s,
                              (bb.x * bb.x + bb.y * bb.y) * inv_s);
  }
  __syncthreads();
  fftr8(sA, sB, tw, tid, false);
  #pragma unroll
  for (int r = 0; r < EPT; ++r) {
    int k = tid + r * TPB;
    float fk = (float)(k < NFFT / 2 ? k : k - NFFT) * (1.0f / NFFT);
    float kk = TWO_PI_F * fk;
    float F = expf(-0.5f * sdt * sdt * kk * kk);
    float2 v = sA[PIDX(k)];
    sA[PIDX(k)] = make_float2(v.x * F, v.y * F);
  }
  __syncthreads();
  fftr8(sA, sB, tw, tid, true);
  #pragma unroll
  for (int r = 0; r < EPT; ++r) {
    int k = tid + r * TPB;
    float2 v = sA[PIDX(k)];
    g_T1[base + k] = v.x * INVN;
    g_T2[base + k] = v.y * INVN;
  }

  // --- cross spectrum smoothing: C = W1*conj(W2)/s (complex)
  #pragma unroll
  for (int r = 0; r < EPT; ++r) {
    int k = tid + r * TPB;
    float2 a = w1[r], bb = w2[r];
    sA[PIDX(k)] = make_float2((a.x * bb.x + a.y * bb.y) * inv_s,
                              (a.y * bb.x - a.x * bb.y) * inv_s);
  }
  __syncthreads();
  fftr8(sA, sB, tw, tid, false);
  #pragma unroll
  for (int r = 0; r < EPT; ++r) {
    int k = tid + r * TPB;
    float fk = (float)(k < NFFT / 2 ? k : k - NFFT) * (1.0f / NFFT);
    float kk = TWO_PI_F * fk;
    float F = expf(-0.5f * sdt * sdt * kk * kk);
    float2 v = sA[PIDX(k)];
    sA[PIDX(k)] = make_float2(v.x * F, v.y * F);
  }
  __syncthreads();
  fftr8(sA, sB, tw, tid, true);
  #pragma unroll
  for (int r = 0; r < EPT; ++r) {
    int k = tid + r * TPB;
    float2 v = sA[PIDX(k)];
    g_T12[base + k] = make_float2(v.x * INVN, v.y * INVN);
  }
}

// ---------------- K3: scale smoothing + coherence + sum over scales -----------
// Window along scales: [.5,1,...,1,.5] at offsets i-5..i+4 (clipped). The 1/9
// normalization cancels in |S12|^2/(S1*S2). Single-pass ring-buffer version:
// each T element loaded exactly once.
// FIX vs R5: subtract outgoing j=i-6 BEFORE loading incoming j=i+4 — they share
// ring slot ((i+4) mod 10 == (i-6) mod 10).
__global__ void kern_coh() {
  const int b = blockIdx.y;
  const int t = blockIdx.x * TPB + threadIdx.x;
  const size_t bb = (size_t)b * NS * NFFT + t;

  float r1[10], r2[10], rcr[10], rci[10];
  float s1 = 0.f, s2 = 0.f, scr = 0.f, sci = 0.f;   // plain sums over clipped window

  #pragma unroll
  for (int j = 0; j < 4; ++j) {
    size_t off = bb + (size_t)j * NFFT;
    float a = g_T1[off], c = g_T2[off];
    float2 d = g_T12[off];
    r1[j] = a; r2[j] = c; rcr[j] = d.x; rci[j] = d.y;
    s1 += a; s2 += c; scr += d.x; sci += d.y;
  }

  float acc = 0.f;
  #pragma unroll
  for (int i = 0; i < NS; ++i) {
    // 1) retire outgoing element j = i-6 (uses OLD slot contents)
    const int jo = i - 6;
    if (jo >= 0) {
      const int ro = jo % 10;
      s1 -= r1[ro]; s2 -= r2[ro]; scr -= rcr[ro]; sci -= rci[ro];
    }
    // 2) load incoming element j = i+4 (may overwrite jo's slot — now safe)
    const int jn = i + 4;
    if (jn < NS) {
      size_t off = bb + (size_t)jn * NFFT;
      float a = g_T1[off], c = g_T2[off];
      float2 d = g_T12[off];
      const int rn = jn % 10;
      r1[rn] = a; r2[rn] = c; rcr[rn] = d.x; rci[rn] = d.y;
      s1 += a; s2 += c; scr += d.x; sci += d.y;
    }
    // 3) half-weight end corrections
    float e1 = s1, e2 = s2, ecr = scr, eci = sci;
    const int jl = i - 5;
    if (jl >= 0) {
      const int rl = jl % 10;
      e1 -= 0.5f * r1[rl]; e2 -= 0.5f * r2[rl];
      ecr -= 0.5f * rcr[rl]; eci -= 0.5f * rci[rl];
    }
    if (jn < NS) {
      const int rn = jn % 10;
      e1 -= 0.5f * r1[rn]; e2 -= 0.5f * r2[rn];
      ecr -= 0.5f * rcr[rn]; eci -= 0.5f * rci[rn];
    }
    acc += (ecr * ecr + eci * eci) / (e1 * e2);
  }
  g_coh[(size_t)b * NFFT + t] = acc;
}

// ---------------- K4: sliding window sum (WSZ=94), incremental -----------------
__global__ void kern_slide(float* __restrict__ out) {
  __shared__ float sc[NFFT];
  __shared__ float so[NOUT];
  const int b = blockIdx.x;
  const int tid = threadIdx.x;
  #pragma unroll
  for (int r = 0; r < EPT; ++r)
    sc[tid + r * TPB] = g_coh[(size_t)b * NFFT + tid + r * TPB];
  __syncthreads();

  const int i0 = tid * 8;
  if (i0 < NOUT) {
    float s = 0.f;
    #pragma unroll
    for (int k = 0; k < WSZ; ++k) s += sc[i0 + k];
    so[i0] = s;
    const int lim = (NOUT - i0 < 8) ? (NOUT - i0) : 8;
    for (int r = 1; r < lim; ++r) {
      s += sc[i0 + r - 1 + WSZ] - sc[i0 + r - 1];
      so[i0 + r] = s;
    }
  }
  __syncthreads();
  for (int i = tid; i < NOUT; i += TPB)
    out[(size_t)b * NOUT + i] = so[i];
}

// ---------------- launch -------------------------------------------------------
extern "C" void kernel_launch(void* const* d_in, const int* in_sizes, int n_in,
                              void* d_out, int out_size) {
  const float* x = (const float*)d_in[0];
  int B = in_sizes[0] / (2 * NFFT);
  if (B > MAXB) B = MAXB;
  if (B <= 0) return;

  kern_fft_input<<<B * 2, TPB>>>(x);
  kern_scale<<<dim3(NS, B), TPB>>>();
  kern_coh<<<dim3(NFFT / TPB, B), TPB>>>();
  kern_slide<<<B, TPB>>>((float*)d_out);
}

// round 8
// speedup vs baseline: 2.0965x; 1.3455x over previous
#include <cuda_runtime.h>
#include <math.h>

#define NFFT  2048
#define TPB   256
#define EPT   (NFFT / TPB)        // 8 elements per thread
#define MAXB  64
#define NS    81                  // number of scales (J=80 -> 81)
#define WSZ   94                  // sliding window = 32*3 - 2
#define NOUT  (NFFT - WSZ + 1)    // 1955

#define PI_F  3.14159265358979323846f
#define TWO_PI_F 6.28318530717958647692f

// SMEM padding: 1 extra float2 per 8 -> conflict-free radix-8 exchanges
#define PIDX(i) ((i) + ((i) >> 3))
#define PADN  2304                // PIDX(2047)+1 = 2303, rounded

// ---------------- scratch (static device globals; no runtime alloc) ----------
__device__ float2 g_yh[MAXB * 2 * NFFT];          // forward FFT of normalized inputs
__device__ float  g_T1[MAXB * NS * NFFT];         // smooth(|W1|^2/s)
__device__ float  g_T2[MAXB * NS * NFFT];         // smooth(|W2|^2/s)
__device__ float2 g_T12[MAXB * NS * NFFT];        // smooth(W1*conj(W2)/s)
__device__ float  g_coh[MAXB * NFFT];             // coherence summed over scales

// ---------------- complex helpers ---------------------------------------------
__device__ __forceinline__ float2 cadd(float2 a, float2 b){ return make_float2(a.x+b.x, a.y+b.y); }
__device__ __forceinline__ float2 csub(float2 a, float2 b){ return make_float2(a.x-b.x, a.y-b.y); }
__device__ __forceinline__ float2 cmul(float2 a, float2 b){
  return make_float2(a.x*b.x - a.y*b.y, a.x*b.y + a.y*b.x);
}
// multiply by -i (forward) or +i (inverse)
__device__ __forceinline__ float2 rotm(float2 a, bool inv){
  return inv ? make_float2(-a.y, a.x) : make_float2(a.y, -a.x);
}

// radix-8 butterfly core: b[0..7] = DFT8(a[0..7]) (with inv sign convention)
__device__ __forceinline__ void bfly8(const float2* a, float2* b, bool inv) {
  const float C = 0.70710678118654752440f;
  float2 t0 = cadd(a[0],a[4]), t4 = csub(a[0],a[4]);
  float2 t1 = cadd(a[1],a[5]), t5 = csub(a[1],a[5]);
  float2 t2 = cadd(a[2],a[6]), t6 = csub(a[2],a[6]);
  float2 t3 = cadd(a[3],a[7]), t7 = csub(a[3],a[7]);

  const float2 w81 = inv ? make_float2(C,  C) : make_float2(C, -C);
  const float2 w83 = inv ? make_float2(-C, C) : make_float2(-C,-C);
  t5 = cmul(t5, w81);
  t6 = rotm(t6, inv);
  t7 = cmul(t7, w83);

  float2 u0 = cadd(t0,t2), u2 = csub(t0,t2);
  float2 u1 = cadd(t1,t3), u3 = rotm(csub(t1,t3), inv);
  b[0] = cadd(u0,u1); b[4] = csub(u0,u1);
  b[2] = cadd(u2,u3); b[6] = csub(u2,u3);

  float2 v0 = cadd(t4,t6), v2 = csub(t4,t6);
  float2 v1 = cadd(t5,t7), v3 = rotm(csub(t5,t7), inv);
  b[1] = cadd(v0,v1); b[5] = csub(v0,v1);
  b[3] = cadd(v2,v3), b[7] = csub(v2,v3);
}

// twiddle powers w^1..w^7 applied to b[1..7]
__device__ __forceinline__ void twid7(float2* b, float2 w1) {
  float2 w2 = cmul(w1, w1);
  float2 w3 = cmul(w2, w1);
  float2 w4 = cmul(w2, w2);
  float2 w5 = cmul(w3, w2);
  float2 w6 = cmul(w3, w3);
  float2 w7 = cmul(w4, w3);
  b[1] = cmul(b[1], w1); b[2] = cmul(b[2], w2); b[3] = cmul(b[3], w3);
  b[4] = cmul(b[4], w4); b[5] = cmul(b[5], w5); b[6] = cmul(b[6], w6);
  b[7] = cmul(b[7], w7);
}

// ---------------- stage 1 (S=1) from REGISTERS: x[r] = element tid + 256r ------
__device__ __forceinline__ void stage1_reg(const float2* x, float2* dst,
                                           const float2* __restrict__ tw, int tid, bool inv) {
  float2 b[8];
  bfly8(x, b, inv);
  float2 w1 = tw[tid];
  if (inv) w1.y = -w1.y;
  twid7(b, w1);
  const int wb = 8 * tid;
  #pragma unroll
  for (int j = 0; j < 8; ++j) dst[PIDX(wb + j)] = b[j];
}

// ---------------- middle radix-8 Stockham stage (SMEM -> SMEM) -----------------
template<int S>
__device__ __forceinline__ void stage8(const float2* __restrict__ src, float2* __restrict__ dst,
                                       const float2* __restrict__ tw, int tid, bool inv) {
  const int p = tid / S;
  const int q = tid - p * S;
  const int rb = q + S * p;

  float2 a[8];
  #pragma unroll
  for (int k = 0; k < 8; ++k) a[k] = src[PIDX(rb + 256 * k)];

  float2 b[8];
  bfly8(a, b, inv);
  float2 w1 = tw[p * S];
  if (inv) w1.y = -w1.y;
  twid7(b, w1);

  const int wb = q + S * 8 * p;
  #pragma unroll
  for (int j = 0; j < 8; ++j) dst[PIDX(wb + j * S)] = b[j];
}

// ---------------- final radix-4 stage (S=512, trivial twiddles) to REGISTERS ---
// output y[r] = element tid + 256r
__device__ __forceinline__ void stage4_reg(const float2* __restrict__ src, float2* y,
                                           int tid, bool inv) {
  #pragma unroll
  for (int rr = 0; rr < 2; ++rr) {
    const int q = tid + rr * TPB;
    float2 a0 = src[PIDX(q)];
    float2 a1 = src[PIDX(q +  512)];
    float2 a2 = src[PIDX(q + 1024)];
    float2 a3 = src[PIDX(q + 1536)];
    float2 t0 = cadd(a0,a2), t1 = csub(a0,a2);
    float2 t2 = cadd(a1,a3), t3 = rotm(csub(a1,a3), inv);
    y[rr + 0] = cadd(t0,t2);   // element q
    y[rr + 2] = cadd(t1,t3);   // element q + 512
    y[rr + 4] = csub(t0,t2);   // element q + 1024
    y[rr + 6] = csub(t1,t3);   // element q + 1536
  }
}

// N=2048 FFT with register endpoints: x[r] (element tid+256r) -> in-place.
// 3 SMEM round-trips, 4 syncs. No 1/N scaling.
__device__ __forceinline__ void fft_reg(float2* x, float2* sA, float2* sB,
                                        const float2* __restrict__ tw, int tid, bool inv) {
  __syncthreads();                                  // protect sB vs previous stage4_reg reads
  stage1_reg(x, sB, tw, tid, inv);  __syncthreads();
  stage8<8> (sB, sA, tw, tid, inv); __syncthreads();
  stage8<64>(sA, sB, tw, tid, inv); __syncthreads();
  stage4_reg(sB, x, tid, inv);
}

__device__ __forceinline__ void build_tw(float2* tw, int tid) {
  #pragma unroll
  for (int r = 0; r < 4; ++r) {
    int j = tid + r * TPB;
    float sv, cv;
    sincosf(-PI_F * (float)j * (1.0f / 1024.0f), &sv, &cv);
    tw[j] = make_float2(cv, sv);
  }
}

// ---------------- K1: normalize + forward FFT of each input signal ------------
__global__ void kern_fft_input(const float* __restrict__ x) {
  __shared__ float2 sA[PADN];
  __shared__ float2 sB[PADN];
  __shared__ float2 tw[NFFT / 2];
  __shared__ float  red[TPB];
  const int bc  = blockIdx.x;   // b*2 + channel
  const int tid = threadIdx.x;

  build_tw(tw, tid);

  const float* y = x + (size_t)bc * NFFT;
  float vals[EPT];
  float sum = 0.f, sumsq = 0.f;
  #pragma unroll
  for (int r = 0; r < EPT; ++r) {
    float v = y[tid + r * TPB];
    vals[r] = v;
    sum += v;
    sumsq += v * v;
  }
  red[tid] = sum; __syncthreads();
  for (int o = TPB / 2; o > 0; o >>= 1) { if (tid < o) red[tid] += red[tid + o]; __syncthreads(); }
  float mean = red[0] * (1.0f / NFFT);
  __syncthreads();
  red[tid] = sumsq; __syncthreads();
  for (int o = TPB / 2; o > 0; o >>= 1) { if (tid < o) red[tid] += red[tid + o]; __syncthreads(); }
  float var = red[0] * (1.0f / NFFT) - mean * mean;
  float istd = rsqrtf(var);

  float2 z[EPT];
  #pragma unroll
  for (int r = 0; r < EPT; ++r)
    z[r] = make_float2((vals[r] - mean) * istd, 0.f);

  fft_reg(z, sA, sB, tw, tid, false);

  #pragma unroll
  for (int r = 0; r < EPT; ++r)
    g_yh[(size_t)bc * NFFT + tid + r * TPB] = z[r];
}

// ---------------- K2: per (batch, scale) CWT + time smoothing -----------------
__global__ void __launch_bounds__(TPB) kern_scale() {
  __shared__ float2 sA[PADN];
  __shared__ float2 sB[PADN];
  __shared__ float2 tw[NFFT / 2];
  const int si  = blockIdx.x;   // scale index
  const int b   = blockIdx.y;   // batch
  const int tid = threadIdx.x;

  build_tw(tw, tid);

  const double s0d = 2.0 * 0.1 * (6.0 + sqrt(38.0)) / (4.0 * 3.14159265358979323846);
  const float  sc    = (float)(s0d * exp2(0.125 * (double)si));
  const float  inv_s = 1.0f / sc;
  const float  norm  = sqrtf(TWO_PI_F * sc * 10.0f) * 0.75112554446494248f;
  const float  sdt   = sc * 10.0f;
  const float  INVN  = 1.0f / (float)NFFT;
  // scale for products of two unscaled (no 1/N) inverse-FFT outputs, incl. 1/s
  const float  pscale = INVN * INVN * inv_s;

  float2 x1[EPT], x2[EPT];

  // --- W1, W2 (unscaled by 1/N): ifft( yh * norm * psi_hat ), support k in [1,1023]
  #pragma unroll
  for (int c = 0; c < 2; ++c) {
    float2* xx = c == 0 ? x1 : x2;
    #pragma unroll
    for (int r = 0; r < EPT; ++r) {
      int k = tid + r * TPB;
      float2 v = make_float2(0.f, 0.f);
      if (k >= 1 && k < NFFT / 2) {
        float w = TWO_PI_F * (float)k * (1.0f / 204.8f);
        float d = sc * w - 6.0f;
        float g = norm * expf(-0.5f * d * d);
        float2 yh = g_yh[(size_t)(b * 2 + c) * NFFT + k];
        v = make_float2(yh.x * g, yh.y * g);
      }
      xx[r] = v;
    }
    fft_reg(xx, sA, sB, tw, tid, true);
  }

  const size_t base = ((size_t)b * NS + si) * NFFT;

  // Gaussian time-filter values (incl. 1/N for the subsequent inverse FFT)
  float Fk[EPT];
  #pragma unroll
  for (int r = 0; r < EPT; ++r) {
    int k = tid + r * TPB;
    float fk = (float)(k < NFFT / 2 ? k : k - NFFT) * (1.0f / NFFT);
    float kk = TWO_PI_F * fk;
    Fk[r] = expf(-0.5f * sdt * sdt * kk * kk) * INVN;
  }

  // --- packed power smoothing: P = |W1|^2/s + i*|W2|^2/s (filter real-even)
  {
    float2 p[EPT];
    #pragma unroll
    for (int r = 0; r < EPT; ++r) {
      float2 a = x1[r], bb = x2[r];
      p[r] = make_float2((a.x * a.x + a.y * a.y) * pscale,
                         (bb.x * bb.x + bb.y * bb.y) * pscale);
    }
    fft_reg(p, sA, sB, tw, tid, false);
    #pragma unroll
    for (int r = 0; r < EPT; ++r)
      p[r] = make_float2(p[r].x * Fk[r], p[r].y * Fk[r]);
    fft_reg(p, sA, sB, tw, tid, true);
    #pragma unroll
    for (int r = 0; r < EPT; ++r) {
      int k = tid + r * TPB;
      g_T1[base + k] = p[r].x;
      g_T2[base + k] = p[r].y;
    }
  }

  // --- cross spectrum smoothing: C = W1*conj(W2)/s (complex)
  {
    float2 cxy[EPT];
    #pragma unroll
    for (int r = 0; r < EPT; ++r) {
      float2 a = x1[r], bb = x2[r];
      cxy[r] = make_float2((a.x * bb.x + a.y * bb.y) * pscale,
                           (a.y * bb.x - a.x * bb.y) * pscale);
    }
    fft_reg(cxy, sA, sB, tw, tid, false);
    #pragma unroll
    for (int r = 0; r < EPT; ++r)
      cxy[r] = make_float2(cxy[r].x * Fk[r], cxy[r].y * Fk[r]);
    fft_reg(cxy, sA, sB, tw, tid, true);
    #pragma unroll
    for (int r = 0; r < EPT; ++r)
      g_T12[base + tid + r * TPB] = cxy[r];
  }
}

// ---------------- K3: scale smoothing + coherence + sum over scales -----------
// Window along scales: [.5,1,...,1,.5] at offsets i-5..i+4 (clipped). The 1/9
// normalization cancels in |S12|^2/(S1*S2). Single-pass ring buffer; outgoing
// element retired BEFORE the incoming one overwrites its shared slot.
__global__ void kern_coh() {
  const int b = blockIdx.y;
  const int t = blockIdx.x * TPB + threadIdx.x;
  const size_t bb = (size_t)b * NS * NFFT + t;

  float r1[10], r2[10], rcr[10], rci[10];
  float s1 = 0.f, s2 = 0.f, scr = 0.f, sci = 0.f;

  #pragma unroll
  for (int j = 0; j < 4; ++j) {
    size_t off = bb + (size_t)j * NFFT;
    float a = g_T1[off], c = g_T2[off];
    float2 d = g_T12[off];
    r1[j] = a; r2[j] = c; rcr[j] = d.x; rci[j] = d.y;
    s1 += a; s2 += c; scr += d.x; sci += d.y;
  }

  float acc = 0.f;
  #pragma unroll
  for (int i = 0; i < NS; ++i) {
    const int jo = i - 6;
    if (jo >= 0) {
      const int ro = jo % 10;
      s1 -= r1[ro]; s2 -= r2[ro]; scr -= rcr[ro]; sci -= rci[ro];
    }
    const int jn = i + 4;
    if (jn < NS) {
      size_t off = bb + (size_t)jn * NFFT;
      float a = g_T1[off], c = g_T2[off];
      float2 d = g_T12[off];
      const int rn = jn % 10;
      r1[rn] = a; r2[rn] = c; rcr[rn] = d.x; rci[rn] = d.y;
      s1 += a; s2 += c; scr += d.x; sci += d.y;
    }
    float e1 = s1, e2 = s2, ecr = scr, eci = sci;
    const int jl = i - 5;
    if (jl >= 0) {
      const int rl = jl % 10;
      e1 -= 0.5f * r1[rl]; e2 -= 0.5f * r2[rl];
      ecr -= 0.5f * rcr[rl]; eci -= 0.5f * rci[rl];
    }
    if (jn < NS) {
      const int rn = jn % 10;
      e1 -= 0.5f * r1[rn]; e2 -= 0.5f * r2[rn];
      ecr -= 0.5f * rcr[rn]; eci -= 0.5f * rci[rn];
    }
    acc += (ecr * ecr + eci * eci) / (e1 * e2);
  }
  g_coh[(size_t)b * NFFT + t] = acc;
}

// ---------------- K4: sliding window sum (WSZ=94), incremental -----------------
__global__ void kern_slide(float* __restrict__ out) {
  __shared__ float sc[NFFT];
  __shared__ float so[NOUT];
  const int b = blockIdx.x;
  const int tid = threadIdx.x;
  #pragma unroll
  for (int r = 0; r < EPT; ++r)
    sc[tid + r * TPB] = g_coh[(size_t)b * NFFT + tid + r * TPB];
  __syncthreads();

  const int i0 = tid * 8;
  if (i0 < NOUT) {
    float s = 0.f;
    #pragma unroll
    for (int k = 0; k < WSZ; ++k) s += sc[i0 + k];
    so[i0] = s;
    const int lim = (NOUT - i0 < 8) ? (NOUT - i0) : 8;
    for (int r = 1; r < lim; ++r) {
      s += sc[i0 + r - 1 + WSZ] - sc[i0 + r - 1];
      so[i0 + r] = s;
    }
  }
  __syncthreads();
  for (int i = tid; i < NOUT; i += TPB)
    out[(size_t)b * NOUT + i] = so[i];
}

// ---------------- launch -------------------------------------------------------
extern "C" void kernel_launch(void* const* d_in, const int* in_sizes, int n_in,
                              void* d_out, int out_size) {
  const float* x = (const float*)d_in[0];
  int B = in_sizes[0] / (2 * NFFT);
  if (B > MAXB) B = MAXB;
  if (B <= 0) return;

  kern_fft_input<<<B * 2, TPB>>>(x);
  kern_scale<<<dim3(NS, B), TPB>>>();
  kern_coh<<<dim3(NFFT / TPB, B), TPB>>>();
  kern_slide<<<B, TPB>>>((float*)d_out);
}

// round 9
// speedup vs baseline: 2.0984x; 1.0009x over previous
#include <cuda_runtime.h>
#include <math.h>

#define NFFT  2048
#define TPB   256
#define EPT   (NFFT / TPB)        // 8 elements per thread
#define MAXB  64
#define NS    81                  // number of scales (J=80 -> 81)
#define WSZ   94                  // sliding window = 32*3 - 2
#define NOUT  (NFFT - WSZ + 1)    // 1955

#define PI_F  3.14159265358979323846f
#define TWO_PI_F 6.28318530717958647692f

// SMEM padding: 1 extra float2 per 8 -> conflict-free radix-8 exchanges
#define PIDX(i) ((i) + ((i) >> 3))
#define PADN  2304                // PIDX(2047)+1 = 2303, rounded

// ---------------- scratch (static device globals; no runtime alloc) ----------
__device__ float2 g_tw[256];                      // twiddles e^{-i pi j / 1024}
__device__ float2 g_yh[MAXB * 2 * NFFT];          // forward FFT of normalized inputs
__device__ float  g_T1[MAXB * NS * NFFT];         // smooth(|W1|^2/s)
__device__ float  g_T2[MAXB * NS * NFFT];         // smooth(|W2|^2/s)
__device__ float2 g_T12[MAXB * NS * NFFT];        // smooth(W1*conj(W2)/s)
__device__ float  g_coh[MAXB * NFFT];             // coherence summed over scales

// ---------------- complex helpers ---------------------------------------------
__device__ __forceinline__ float2 cadd(float2 a, float2 b){ return make_float2(a.x+b.x, a.y+b.y); }
__device__ __forceinline__ float2 csub(float2 a, float2 b){ return make_float2(a.x-b.x, a.y-b.y); }
__device__ __forceinline__ float2 cmul(float2 a, float2 b){
  return make_float2(a.x*b.x - a.y*b.y, a.x*b.y + a.y*b.x);
}
// multiply by -i (forward) or +i (inverse)
__device__ __forceinline__ float2 rotm(float2 a, bool inv){
  return inv ? make_float2(-a.y, a.x) : make_float2(a.y, -a.x);
}

// second half of the radix-8 butterfly given t0..t7 (t5,t6,t7 already rotated)
__device__ __forceinline__ void bfly8_tail(float2 t0, float2 t1, float2 t2, float2 t3,
                                           float2 t4, float2 t5, float2 t6, float2 t7,
                                           float2* b, bool inv) {
  float2 u0 = cadd(t0,t2), u2 = csub(t0,t2);
  float2 u1 = cadd(t1,t3), u3 = rotm(csub(t1,t3), inv);
  b[0] = cadd(u0,u1); b[4] = csub(u0,u1);
  b[2] = cadd(u2,u3); b[6] = csub(u2,u3);

  float2 v0 = cadd(t4,t6), v2 = csub(t4,t6);
  float2 v1 = cadd(t5,t7), v3 = rotm(csub(t5,t7), inv);
  b[1] = cadd(v0,v1); b[5] = csub(v0,v1);
  b[3] = cadd(v2,v3); b[7] = csub(v2,v3);
}

// radix-8 butterfly core: b[0..7] = DFT8(a[0..7]) (with inv sign convention)
__device__ __forceinline__ void bfly8(const float2* a, float2* b, bool inv) {
  const float C = 0.70710678118654752440f;
  float2 t0 = cadd(a[0],a[4]), t4 = csub(a[0],a[4]);
  float2 t1 = cadd(a[1],a[5]), t5 = csub(a[1],a[5]);
  float2 t2 = cadd(a[2],a[6]), t6 = csub(a[2],a[6]);
  float2 t3 = cadd(a[3],a[7]), t7 = csub(a[3],a[7]);
  const float2 w81 = inv ? make_float2(C,  C) : make_float2(C, -C);
  const float2 w83 = inv ? make_float2(-C, C) : make_float2(-C,-C);
  bfly8_tail(t0, t1, t2, t3, t4, cmul(t5, w81), rotm(t6, inv), cmul(t7, w83), b, inv);
}

// radix-8 butterfly with a[4..7] == 0 (half-spectrum inverse first stage)
__device__ __forceinline__ void bfly8_half(const float2* a, float2* b, bool inv) {
  const float C = 0.70710678118654752440f;
  const float2 w81 = inv ? make_float2(C,  C) : make_float2(C, -C);
  const float2 w83 = inv ? make_float2(-C, C) : make_float2(-C,-C);
  bfly8_tail(a[0], a[1], a[2], a[3], a[0], cmul(a[1], w81), rotm(a[2], inv), cmul(a[3], w83), b, inv);
}

// twiddle powers w^1..w^7 applied to b[1..7]
__device__ __forceinline__ void twid7(float2* b, float2 w1) {
  float2 w2 = cmul(w1, w1);
  float2 w3 = cmul(w2, w1);
  float2 w4 = cmul(w2, w2);
  float2 w5 = cmul(w3, w2);
  float2 w6 = cmul(w3, w3);
  float2 w7 = cmul(w4, w3);
  b[1] = cmul(b[1], w1); b[2] = cmul(b[2], w2); b[3] = cmul(b[3], w3);
  b[4] = cmul(b[4], w4); b[5] = cmul(b[5], w5); b[6] = cmul(b[6], w6);
  b[7] = cmul(b[7], w7);
}

// ---------------- stage 1 (S=1) from REGISTERS: x[r] = element tid + 256r ------
template<bool HALF>
__device__ __forceinline__ void stage1_reg(const float2* x, float2* dst,
                                           const float2* __restrict__ tw, int tid, bool inv) {
  float2 b[8];
  if (HALF) bfly8_half(x, b, inv); else bfly8(x, b, inv);
  float2 w1 = tw[tid];
  if (inv) w1.y = -w1.y;
  twid7(b, w1);
  const int wb = 8 * tid;
  #pragma unroll
  for (int j = 0; j < 8; ++j) dst[PIDX(wb + j)] = b[j];
}

// ---------------- middle radix-8 Stockham stage (SMEM -> SMEM) -----------------
template<int S>
__device__ __forceinline__ void stage8(const float2* __restrict__ src, float2* __restrict__ dst,
                                       const float2* __restrict__ tw, int tid, bool inv) {
  const int p = tid / S;
  const int q = tid - p * S;
  const int rb = q + S * p;

  float2 a[8];
  #pragma unroll
  for (int k = 0; k < 8; ++k) a[k] = src[PIDX(rb + 256 * k)];

  float2 b[8];
  bfly8(a, b, inv);
  float2 w1 = tw[p * S];
  if (inv) w1.y = -w1.y;
  twid7(b, w1);

  const int wb = q + S * 8 * p;
  #pragma unroll
  for (int j = 0; j < 8; ++j) dst[PIDX(wb + j * S)] = b[j];
}

// ---------------- final radix-4 stage (S=512, trivial twiddles) to REGISTERS ---
// output y[r] = element tid + 256r
__device__ __forceinline__ void stage4_reg(const float2* __restrict__ src, float2* y,
                                           int tid, bool inv) {
  #pragma unroll
  for (int rr = 0; rr < 2; ++rr) {
    const int q = tid + rr * TPB;
    float2 a0 = src[PIDX(q)];
    float2 a1 = src[PIDX(q +  512)];
    float2 a2 = src[PIDX(q + 1024)];
    float2 a3 = src[PIDX(q + 1536)];
    float2 t0 = cadd(a0,a2), t1 = csub(a0,a2);
    float2 t2 = cadd(a1,a3), t3 = rotm(csub(a1,a3), inv);
    y[rr + 0] = cadd(t0,t2);   // element q
    y[rr + 2] = cadd(t1,t3);   // element q + 512
    y[rr + 4] = csub(t0,t2);   // element q + 1024
    y[rr + 6] = csub(t1,t3);   // element q + 1536
  }
}

// N=2048 FFT with register endpoints: x[r] (element tid+256r) -> in-place.
// 3 SMEM round-trips, 4 syncs. No 1/N scaling.
template<bool HALF>
__device__ __forceinline__ void fft_reg(float2* x, float2* sA, float2* sB,
                                        const float2* __restrict__ tw, int tid, bool inv) {
  __syncthreads();                                  // protect sB vs previous stage4_reg reads
  stage1_reg<HALF>(x, sB, tw, tid, inv);  __syncthreads();
  stage8<8> (sB, sA, tw, tid, inv); __syncthreads();
  stage8<64>(sA, sB, tw, tid, inv); __syncthreads();
  stage4_reg(sB, x, tid, inv);
}

// ---------------- K0: build 256-entry twiddle table (double precision) ---------
__global__ void kern_init_tw() {
  const int j = threadIdx.x;
  double a = -3.14159265358979323846 * (double)j / 1024.0;
  g_tw[j] = make_float2((float)cos(a), (float)sin(a));
}

// ---------------- K1: normalize + forward FFT of each input signal ------------
__global__ void kern_fft_input(const float* __restrict__ x) {
  __shared__ float2 sA[PADN];
  __shared__ float2 sB[PADN];
  __shared__ float2 tw[256];
  __shared__ float  red[TPB];
  const int bc  = blockIdx.x;   // b*2 + channel
  const int tid = threadIdx.x;

  tw[tid] = g_tw[tid];

  const float* y = x + (size_t)bc * NFFT;
  float vals[EPT];
  float sum = 0.f, sumsq = 0.f;
  #pragma unroll
  for (int r = 0; r < EPT; ++r) {
    float v = y[tid + r * TPB];
    vals[r] = v;
    sum += v;
    sumsq += v * v;
  }
  red[tid] = sum; __syncthreads();
  for (int o = TPB / 2; o > 0; o >>= 1) { if (tid < o) red[tid] += red[tid + o]; __syncthreads(); }
  float mean = red[0] * (1.0f / NFFT);
  __syncthreads();
  red[tid] = sumsq; __syncthreads();
  for (int o = TPB / 2; o > 0; o >>= 1) { if (tid < o) red[tid] += red[tid + o]; __syncthreads(); }
  float var = red[0] * (1.0f / NFFT) - mean * mean;
  float istd = rsqrtf(var);

  float2 z[EPT];
  #pragma unroll
  for (int r = 0; r < EPT; ++r)
    z[r] = make_float2((vals[r] - mean) * istd, 0.f);

  fft_reg<false>(z, sA, sB, tw, tid, false);

  #pragma unroll
  for (int r = 0; r < EPT; ++r)
    g_yh[(size_t)bc * NFFT + tid + r * TPB] = z[r];
}

// ---------------- K2: per (batch, scale) CWT + time smoothing -----------------
__global__ void __launch_bounds__(TPB) kern_scale() {
  __shared__ float2 sA[PADN];
  __shared__ float2 sB[PADN];
  __shared__ float2 tw[256];
  const int si  = blockIdx.x;   // scale index
  const int b   = blockIdx.y;   // batch
  const int tid = threadIdx.x;

  tw[tid] = g_tw[tid];

  const double s0d = 2.0 * 0.1 * (6.0 + sqrt(38.0)) / (4.0 * 3.14159265358979323846);
  const float  sc    = (float)(s0d * exp2(0.125 * (double)si));
  const float  inv_s = 1.0f / sc;
  const float  norm  = sqrtf(TWO_PI_F * sc * 10.0f) * 0.75112554446494248f;
  const float  sdt   = sc * 10.0f;
  const float  INVN  = 1.0f / (float)NFFT;
  // scale for products of two unscaled (no 1/N) inverse-FFT outputs, incl. 1/s
  const float  pscale = INVN * INVN * inv_s;

  float2 x1[EPT], x2[EPT];

  // --- W1, W2 (unscaled by 1/N): ifft( yh * norm * psi_hat ), support k in [1,1023]
  #pragma unroll
  for (int c = 0; c < 2; ++c) {
    float2* xx = c == 0 ? x1 : x2;
    #pragma unroll
    for (int r = 0; r < 4; ++r) {        // only k < 1024 nonzero
      int k = tid + r * TPB;
      float2 v = make_float2(0.f, 0.f);
      if (k >= 1) {
        float w = TWO_PI_F * (float)k * (1.0f / 204.8f);
        float d = sc * w - 6.0f;
        float g = norm * __expf(-0.5f * d * d);
        float2 yh = g_yh[(size_t)(b * 2 + c) * NFFT + k];
        v = make_float2(yh.x * g, yh.y * g);
      }
      xx[r] = v;
    }
    #pragma unroll
    for (int r = 4; r < EPT; ++r) xx[r] = make_float2(0.f, 0.f);
    fft_reg<true>(xx, sA, sB, tw, tid, true);
  }

  const size_t base = ((size_t)b * NS + si) * NFFT;

  // Gaussian time-filter values (incl. 1/N for the subsequent inverse FFT)
  float Fk[EPT];
  #pragma unroll
  for (int r = 0; r < EPT; ++r) {
    int k = tid + r * TPB;
    float fk = (float)(k < NFFT / 2 ? k : k - NFFT) * (1.0f / NFFT);
    float kk = TWO_PI_F * fk;
    Fk[r] = __expf(-0.5f * sdt * sdt * kk * kk) * INVN;
  }

  // --- packed power smoothing: P = |W1|^2/s + i*|W2|^2/s (filter real-even)
  {
    float2 p[EPT];
    #pragma unroll
    for (int r = 0; r < EPT; ++r) {
      float2 a = x1[r], bb = x2[r];
      p[r] = make_float2((a.x * a.x + a.y * a.y) * pscale,
                         (bb.x * bb.x + bb.y * bb.y) * pscale);
    }
    fft_reg<false>(p, sA, sB, tw, tid, false);
    #pragma unroll
    for (int r = 0; r < EPT; ++r)
      p[r] = make_float2(p[r].x * Fk[r], p[r].y * Fk[r]);
    fft_reg<false>(p, sA, sB, tw, tid, true);
    #pragma unroll
    for (int r = 0; r < EPT; ++r) {
      int k = tid + r * TPB;
      g_T1[base + k] = p[r].x;
      g_T2[base + k] = p[r].y;
    }
  }

  // --- cross spectrum smoothing: C = W1*conj(W2)/s (complex)
  {
    float2 cxy[EPT];
    #pragma unroll
    for (int r = 0; r < EPT; ++r) {
      float2 a = x1[r], bb = x2[r];
      cxy[r] = make_float2((a.x * bb.x + a.y * bb.y) * pscale,
                           (a.y * bb.x - a.x * bb.y) * pscale);
    }
    fft_reg<false>(cxy, sA, sB, tw, tid, false);
    #pragma unroll
    for (int r = 0; r < EPT; ++r)
      cxy[r] = make_float2(cxy[r].x * Fk[r], cxy[r].y * Fk[r]);
    fft_reg<false>(cxy, sA, sB, tw, tid, true);
    #pragma unroll
    for (int r = 0; r < EPT; ++r)
      g_T12[base + tid + r * TPB] = cxy[r];
  }
}

// ---------------- K3: scale smoothing + coherence + sum over scales -----------
// Window along scales: [.5,1,...,1,.5] at offsets i-5..i+4 (clipped). The 1/9
// normalization cancels in |S12|^2/(S1*S2). Single-pass ring buffer; outgoing
// element retired BEFORE the incoming one overwrites its shared slot.
__global__ void kern_coh() {
  const int b = blockIdx.y;
  const int t = blockIdx.x * TPB + threadIdx.x;
  const size_t bb = (size_t)b * NS * NFFT + t;

  float r1[10], r2[10], rcr[10], rci[10];
  float s1 = 0.f, s2 = 0.f, scr = 0.f, sci = 0.f;

  #pragma unroll
  for (int j = 0; j < 4; ++j) {
    size_t off = bb + (size_t)j * NFFT;
    float a = g_T1[off], c = g_T2[off];
    float2 d = g_T12[off];
    r1[j] = a; r2[j] = c; rcr[j] = d.x; rci[j] = d.y;
    s1 += a; s2 += c; scr += d.x; sci += d.y;
  }

  float acc = 0.f;
  #pragma unroll
  for (int i = 0; i < NS; ++i) {
    const int jo = i - 6;
    if (jo >= 0) {
      const int ro = jo % 10;
      s1 -= r1[ro]; s2 -= r2[ro]; scr -= rcr[ro]; sci -= rci[ro];
    }
    const int jn = i + 4;
    if (jn < NS) {
      size_t off = bb + (size_t)jn * NFFT;
      float a = g_T1[off], c = g_T2[off];
      float2 d = g_T12[off];
      const int rn = jn % 10;
      r1[rn] = a; r2[rn] = c; rcr[rn] = d.x; rci[rn] = d.y;
      s1 += a; s2 += c; scr += d.x; sci += d.y;
    }
    float e1 = s1, e2 = s2, ecr = scr, eci = sci;
    const int jl = i - 5;
    if (jl >= 0) {
      const int rl = jl % 10;
      e1 -= 0.5f * r1[rl]; e2 -= 0.5f * r2[rl];
      ecr -= 0.5f * rcr[rl]; eci -= 0.5f * rci[rl];
    }
    if (jn < NS) {
      const int rn = jn % 10;
      e1 -= 0.5f * r1[rn]; e2 -= 0.5f * r2[rn];
      ecr -= 0.5f * rcr[rn]; eci -= 0.5f * rci[rn];
    }
    acc += (ecr * ecr + eci * eci) / (e1 * e2);
  }
  g_coh[(size_t)b * NFFT + t] = acc;
}

// ---------------- K4: sliding window sum (WSZ=94), incremental -----------------
__global__ void kern_slide(float* __restrict__ out) {
  __shared__ float sc[NFFT];
  __shared__ float so[NOUT];
  const int b = blockIdx.x;
  const int tid = threadIdx.x;
  #pragma unroll
  for (int r = 0; r < EPT; ++r)
    sc[tid + r * TPB] = g_coh[(size_t)b * NFFT + tid + r * TPB];
  __syncthreads();

  const int i0 = tid * 8;
  if (i0 < NOUT) {
    float s = 0.f;
    #pragma unroll
    for (int k = 0; k < WSZ; ++k) s += sc[i0 + k];
    so[i0] = s;
    const int lim = (NOUT - i0 < 8) ? (NOUT - i0) : 8;
    for (int r = 1; r < lim; ++r) {
      s += sc[i0 + r - 1 + WSZ] - sc[i0 + r - 1];
      so[i0 + r] = s;
    }
  }
  __syncthreads();
  for (int i = tid; i < NOUT; i += TPB)
    out[(size_t)b * NOUT + i] = so[i];
}

// ---------------- launch -------------------------------------------------------
extern "C" void kernel_launch(void* const* d_in, const int* in_sizes, int n_in,
                              void* d_out, int out_size) {
  const float* x = (const float*)d_in[0];
  int B = in_sizes[0] / (2 * NFFT);
  if (B > MAXB) B = MAXB;
  if (B <= 0) return;

  kern_init_tw<<<1, 256>>>();
  kern_fft_input<<<B * 2, TPB>>>(x);
  kern_scale<<<dim3(NS, B), TPB>>>();
  kern_coh<<<dim3(NFFT / TPB, B), TPB>>>();
  kern_slide<<<B, TPB>>>((float*)d_out);
}

// round 10
// speedup vs baseline: 2.1033x; 1.0023x over previous
#include <cuda_runtime.h>
#include <math.h>

#define NFFT  2048
#define TPB   256
#define EPT   (NFFT / TPB)        // 8 elements per thread
#define MAXB  64
#define NS    81                  // number of scales (J=80 -> 81)
#define WSZ   94                  // sliding window = 32*3 - 2
#define NOUT  (NFFT - WSZ + 1)    // 1955

#define PI_F  3.14159265358979323846f
#define TWO_PI_F 6.28318530717958647692f

// SMEM padding: 1 extra float2 per 8 -> conflict-free radix-8 exchanges
#define PIDX(i) ((i) + ((i) >> 3))
#define PADN  2304                // PIDX(2047)+1 = 2303, rounded

// ---------------- scratch (static device globals; no runtime alloc) ----------
__device__ float2 g_tw[256];                      // twiddles e^{-i pi j / 1024}
__device__ float2 g_yh[MAXB * 2 * NFFT];          // forward FFT of normalized inputs
// interleaved smooth outputs: [b][scale][t][0] = (T1,T2), [b][scale][t][1] = T12
__device__ float2 g_Tp[(size_t)MAXB * NS * NFFT * 2];
__device__ float  g_coh[MAXB * NFFT];             // coherence summed over scales

// ---------------- complex helpers ---------------------------------------------
__device__ __forceinline__ float2 cadd(float2 a, float2 b){ return make_float2(a.x+b.x, a.y+b.y); }
__device__ __forceinline__ float2 csub(float2 a, float2 b){ return make_float2(a.x-b.x, a.y-b.y); }
__device__ __forceinline__ float2 cmul(float2 a, float2 b){
  return make_float2(a.x*b.x - a.y*b.y, a.x*b.y + a.y*b.x);
}
// multiply by -i (forward) or +i (inverse)
__device__ __forceinline__ float2 rotm(float2 a, bool inv){
  return inv ? make_float2(-a.y, a.x) : make_float2(a.y, -a.x);
}

// second half of the radix-8 butterfly given t0..t7 (t5,t6,t7 already rotated)
__device__ __forceinline__ void bfly8_tail(float2 t0, float2 t1, float2 t2, float2 t3,
                                           float2 t4, float2 t5, float2 t6, float2 t7,
                                           float2* b, bool inv) {
  float2 u0 = cadd(t0,t2), u2 = csub(t0,t2);
  float2 u1 = cadd(t1,t3), u3 = rotm(csub(t1,t3), inv);
  b[0] = cadd(u0,u1); b[4] = csub(u0,u1);
  b[2] = cadd(u2,u3); b[6] = csub(u2,u3);

  float2 v0 = cadd(t4,t6), v2 = csub(t4,t6);
  float2 v1 = cadd(t5,t7), v3 = rotm(csub(t5,t7), inv);
  b[1] = cadd(v0,v1); b[5] = csub(v0,v1);
  b[3] = cadd(v2,v3); b[7] = csub(v2,v3);
}

// radix-8 butterfly core: b[0..7] = DFT8(a[0..7]) (with inv sign convention)
__device__ __forceinline__ void bfly8(const float2* a, float2* b, bool inv) {
  const float C = 0.70710678118654752440f;
  float2 t0 = cadd(a[0],a[4]), t4 = csub(a[0],a[4]);
  float2 t1 = cadd(a[1],a[5]), t5 = csub(a[1],a[5]);
  float2 t2 = cadd(a[2],a[6]), t6 = csub(a[2],a[6]);
  float2 t3 = cadd(a[3],a[7]), t7 = csub(a[3],a[7]);
  const float2 w81 = inv ? make_float2(C,  C) : make_float2(C, -C);
  const float2 w83 = inv ? make_float2(-C, C) : make_float2(-C,-C);
  bfly8_tail(t0, t1, t2, t3, t4, cmul(t5, w81), rotm(t6, inv), cmul(t7, w83), b, inv);
}

// radix-8 butterfly with a[4..7] == 0 (half-spectrum inverse first stage)
__device__ __forceinline__ void bfly8_half(const float2* a, float2* b, bool inv) {
  const float C = 0.70710678118654752440f;
  const float2 w81 = inv ? make_float2(C,  C) : make_float2(C, -C);
  const float2 w83 = inv ? make_float2(-C, C) : make_float2(-C,-C);
  bfly8_tail(a[0], a[1], a[2], a[3], a[0], cmul(a[1], w81), rotm(a[2], inv), cmul(a[3], w83), b, inv);
}

// twiddle powers w^1..w^7 applied to b[1..7]
__device__ __forceinline__ void twid7(float2* b, float2 w1) {
  float2 w2 = cmul(w1, w1);
  float2 w3 = cmul(w2, w1);
  float2 w4 = cmul(w2, w2);
  float2 w5 = cmul(w3, w2);
  float2 w6 = cmul(w3, w3);
  float2 w7 = cmul(w4, w3);
  b[1] = cmul(b[1], w1); b[2] = cmul(b[2], w2); b[3] = cmul(b[3], w3);
  b[4] = cmul(b[4], w4); b[5] = cmul(b[5], w5); b[6] = cmul(b[6], w6);
  b[7] = cmul(b[7], w7);
}

// ---------------- stage 1 (S=1) from REGISTERS: x[r] = element tid + 256r ------
template<bool HALF>
__device__ __forceinline__ void stage1_reg(const float2* x, float2* dst,
                                           const float2* __restrict__ tw, int tid, bool inv) {
  float2 b[8];
  if (HALF) bfly8_half(x, b, inv); else bfly8(x, b, inv);
  float2 w1 = tw[tid];
  if (inv) w1.y = -w1.y;
  twid7(b, w1);
  const int wb = 8 * tid;
  #pragma unroll
  for (int j = 0; j < 8; ++j) dst[PIDX(wb + j)] = b[j];
}

// ---------------- middle radix-8 Stockham stage (SMEM -> SMEM) -----------------
template<int S>
__device__ __forceinline__ void stage8(const float2* __restrict__ src, float2* __restrict__ dst,
                                       const float2* __restrict__ tw, int tid, bool inv) {
  const int p = tid / S;
  const int q = tid - p * S;
  const int rb = q + S * p;

  float2 a[8];
  #pragma unroll
  for (int k = 0; k < 8; ++k) a[k] = src[PIDX(rb + 256 * k)];

  float2 b[8];
  bfly8(a, b, inv);
  float2 w1 = tw[p * S];
  if (inv) w1.y = -w1.y;
  twid7(b, w1);

  const int wb = q + S * 8 * p;
  #pragma unroll
  for (int j = 0; j < 8; ++j) dst[PIDX(wb + j * S)] = b[j];
}

// ---------------- final radix-4 stage (S=512, trivial twiddles) to REGISTERS ---
// output y[r] = element tid + 256r
__device__ __forceinline__ void stage4_reg(const float2* __restrict__ src, float2* y,
                                           int tid, bool inv) {
  #pragma unroll
  for (int rr = 0; rr < 2; ++rr) {
    const int q = tid + rr * TPB;
    float2 a0 = src[PIDX(q)];
    float2 a1 = src[PIDX(q +  512)];
    float2 a2 = src[PIDX(q + 1024)];
    float2 a3 = src[PIDX(q + 1536)];
    float2 t0 = cadd(a0,a2), t1 = csub(a0,a2);
    float2 t2 = cadd(a1,a3), t3 = rotm(csub(a1,a3), inv);
    y[rr + 0] = cadd(t0,t2);   // element q
    y[rr + 2] = cadd(t1,t3);   // element q + 512
    y[rr + 4] = csub(t0,t2);   // element q + 1024
    y[rr + 6] = csub(t1,t3);   // element q + 1536
  }
}

// N=2048 FFT with register endpoints: x[r] (element tid+256r) -> in-place.
// 3 SMEM round-trips, 4 syncs. No 1/N scaling.
template<bool HALF>
__device__ __forceinline__ void fft_reg(float2* x, float2* sA, float2* sB,
                                        const float2* __restrict__ tw, int tid, bool inv) {
  __syncthreads();                                  // protect sB vs previous stage4_reg reads
  stage1_reg<HALF>(x, sB, tw, tid, inv);  __syncthreads();
  stage8<8> (sB, sA, tw, tid, inv); __syncthreads();
  stage8<64>(sA, sB, tw, tid, inv); __syncthreads();
  stage4_reg(sB, x, tid, inv);
}

// ---------------- K0: build 256-entry twiddle table (double precision) ---------
__global__ void kern_init_tw() {
  const int j = threadIdx.x;
  double a = -3.14159265358979323846 * (double)j / 1024.0;
  g_tw[j] = make_float2((float)cos(a), (float)sin(a));
}

// ---------------- K1: normalize + forward FFT of each input signal ------------
__global__ void kern_fft_input(const float* __restrict__ x) {
  __shared__ float2 sA[PADN];
  __shared__ float2 sB[PADN];
  __shared__ float2 tw[256];
  __shared__ float  red[TPB];
  const int bc  = blockIdx.x;   // b*2 + channel
  const int tid = threadIdx.x;

  tw[tid] = g_tw[tid];

  const float* y = x + (size_t)bc * NFFT;
  float vals[EPT];
  float sum = 0.f, sumsq = 0.f;
  #pragma unroll
  for (int r = 0; r < EPT; ++r) {
    float v = y[tid + r * TPB];
    vals[r] = v;
    sum += v;
    sumsq += v * v;
  }
  red[tid] = sum; __syncthreads();
  for (int o = TPB / 2; o > 0; o >>= 1) { if (tid < o) red[tid] += red[tid + o]; __syncthreads(); }
  float mean = red[0] * (1.0f / NFFT);
  __syncthreads();
  red[tid] = sumsq; __syncthreads();
  for (int o = TPB / 2; o > 0; o >>= 1) { if (tid < o) red[tid] += red[tid + o]; __syncthreads(); }
  float var = red[0] * (1.0f / NFFT) - mean * mean;
  float istd = rsqrtf(var);

  float2 z[EPT];
  #pragma unroll
  for (int r = 0; r < EPT; ++r)
    z[r] = make_float2((vals[r] - mean) * istd, 0.f);

  fft_reg<false>(z, sA, sB, tw, tid, false);

  #pragma unroll
  for (int r = 0; r < EPT; ++r)
    g_yh[(size_t)bc * NFFT + tid + r * TPB] = z[r];
}

// ---------------- K2: per (batch, scale) CWT + time smoothing -----------------
__global__ void __launch_bounds__(TPB, 3) kern_scale() {
  __shared__ float2 sA[PADN];
  __shared__ float2 sB[PADN];
  __shared__ float2 tw[256];
  const int si  = blockIdx.x;   // scale index
  const int b   = blockIdx.y;   // batch
  const int tid = threadIdx.x;

  tw[tid] = g_tw[tid];

  const double s0d = 2.0 * 0.1 * (6.0 + sqrt(38.0)) / (4.0 * 3.14159265358979323846);
  const float  sc    = (float)(s0d * exp2(0.125 * (double)si));
  const float  inv_s = 1.0f / sc;
  const float  norm  = sqrtf(TWO_PI_F * sc * 10.0f) * 0.75112554446494248f;
  const float  sdt   = sc * 10.0f;
  const float  INVN  = 1.0f / (float)NFFT;
  // scale for products of two unscaled (no 1/N) inverse-FFT outputs, incl. 1/s
  const float  pscale = INVN * INVN * inv_s;

  float2 x1[EPT], x2[EPT];

  // --- W1, W2 (unscaled by 1/N): ifft( yh * norm * psi_hat ), support k in [1,1023]
  #pragma unroll
  for (int c = 0; c < 2; ++c) {
    float2* xx = c == 0 ? x1 : x2;
    #pragma unroll
    for (int r = 0; r < 4; ++r) {        // only k < 1024 nonzero
      int k = tid + r * TPB;
      float2 v = make_float2(0.f, 0.f);
      if (k >= 1) {
        float w = TWO_PI_F * (float)k * (1.0f / 204.8f);
        float d = sc * w - 6.0f;
        float g = norm * __expf(-0.5f * d * d);
        float2 yh = g_yh[(size_t)(b * 2 + c) * NFFT + k];
        v = make_float2(yh.x * g, yh.y * g);
      }
      xx[r] = v;
    }
    #pragma unroll
    for (int r = 4; r < EPT; ++r) xx[r] = make_float2(0.f, 0.f);
    fft_reg<true>(xx, sA, sB, tw, tid, true);
  }

  const size_t base = ((size_t)b * NS + si) * NFFT;

  // Gaussian time-filter values (incl. 1/N for the subsequent inverse FFT)
  float Fk[EPT];
  #pragma unroll
  for (int r = 0; r < EPT; ++r) {
    int k = tid + r * TPB;
    float fk = (float)(k < NFFT / 2 ? k : k - NFFT) * (1.0f / NFFT);
    float kk = TWO_PI_F * fk;
    Fk[r] = __expf(-0.5f * sdt * sdt * kk * kk) * INVN;
  }

  // --- packed power smoothing: P = |W1|^2/s + i*|W2|^2/s (filter real-even)
  {
    float2 p[EPT];
    #pragma unroll
    for (int r = 0; r < EPT; ++r) {
      float2 a = x1[r], bb = x2[r];
      p[r] = make_float2((a.x * a.x + a.y * a.y) * pscale,
                         (bb.x * bb.x + bb.y * bb.y) * pscale);
    }
    fft_reg<false>(p, sA, sB, tw, tid, false);
    #pragma unroll
    for (int r = 0; r < EPT; ++r)
      p[r] = make_float2(p[r].x * Fk[r], p[r].y * Fk[r]);
    fft_reg<false>(p, sA, sB, tw, tid, true);
    #pragma unroll
    for (int r = 0; r < EPT; ++r)
      g_Tp[(base + tid + r * TPB) * 2] = p[r];           // (T1, T2)
  }

  // --- cross spectrum smoothing: C = W1*conj(W2)/s (complex)
  {
    float2 cxy[EPT];
    #pragma unroll
    for (int r = 0; r < EPT; ++r) {
      float2 a = x1[r], bb = x2[r];
      cxy[r] = make_float2((a.x * bb.x + a.y * bb.y) * pscale,
                           (a.y * bb.x - a.x * bb.y) * pscale);
    }
    fft_reg<false>(cxy, sA, sB, tw, tid, false);
    #pragma unroll
    for (int r = 0; r < EPT; ++r)
      cxy[r] = make_float2(cxy[r].x * Fk[r], cxy[r].y * Fk[r]);
    fft_reg<false>(cxy, sA, sB, tw, tid, true);
    #pragma unroll
    for (int r = 0; r < EPT; ++r)
      g_Tp[(base + tid + r * TPB) * 2 + 1] = cxy[r];     // T12
  }
}

// ---------------- K3: scale smoothing + coherence + sum over scales -----------
// Pair-split: even lane of each pair carries (T1,T2), odd lane carries T12.
// Window along scales: [.5,1,...,1,.5] at offsets i-5..i+4 (clipped); the 1/9
// normalization cancels in |S12|^2/(S1*S2). Ring depth 10 per 2 streams ->
// ~half the registers of the 4-stream version; num/den combined via shfl.
__global__ void __launch_bounds__(TPB) kern_coh() {
  const int b   = blockIdx.y;
  const int sub = threadIdx.x & 1;                    // 0: (T1,T2), 1: T12
  const int t   = blockIdx.x * (TPB / 2) + (threadIdx.x >> 1);
  const size_t base = ((size_t)b * NS * NFFT + t) * 2 + sub;
  const size_t step = (size_t)NFFT * 2;

  float ru[10], rv[10];
  float su = 0.f, sv = 0.f;

  #pragma unroll
  for (int j = 0; j < 4; ++j) {
    float2 d = g_Tp[base + (size_t)j * step];
    ru[j] = d.x; rv[j] = d.y; su += d.x; sv += d.y;
  }

  float acc = 0.f;
  #pragma unroll
  for (int i = 0; i < NS; ++i) {
    // retire outgoing j = i-6 BEFORE loading j = i+4 (shared ring slot mod 10)
    const int jo = i - 6;
    if (jo >= 0) {
      const int ro = jo % 10;
      su -= ru[ro]; sv -= rv[ro];
    }
    const int jn = i + 4;
    if (jn < NS) {
      float2 d = g_Tp[base + (size_t)jn * step];
      const int rn = jn % 10;
      ru[rn] = d.x; rv[rn] = d.y; su += d.x; sv += d.y;
    }
    float eu = su, ev = sv;
    const int jl = i - 5;
    if (jl >= 0) {
      const int rl = jl % 10;
      eu -= 0.5f * ru[rl]; ev -= 0.5f * rv[rl];
    }
    if (jn < NS) {
      const int rn = jn % 10;
      eu -= 0.5f * ru[rn]; ev -= 0.5f * rv[rn];
    }
    // even lane: den = S1*S2 ; odd lane: num = |S12|^2
    float val = sub ? (eu * eu + ev * ev) : (eu * ev);
    float other = __shfl_xor_sync(0xffffffffu, val, 1);
    acc += sub ? (val / other) : (other / val);
  }
  if (!sub) g_coh[(size_t)b * NFFT + t] = acc;
}

// ---------------- K4: sliding window sum (WSZ=94), incremental -----------------
__global__ void kern_slide(float* __restrict__ out) {
  __shared__ float sc[NFFT];
  __shared__ float so[NOUT];
  const int b = blockIdx.x;
  const int tid = threadIdx.x;
  #pragma unroll
  for (int r = 0; r < EPT; ++r)
    sc[tid + r * TPB] = g_coh[(size_t)b * NFFT + tid + r * TPB];
  __syncthreads();

  const int i0 = tid * 8;
  if (i0 < NOUT) {
    float s = 0.f;
    #pragma unroll
    for (int k = 0; k < WSZ; ++k) s += sc[i0 + k];
    so[i0] = s;
    const int lim = (NOUT - i0 < 8) ? (NOUT - i0) : 8;
    for (int r = 1; r < lim; ++r) {
      s += sc[i0 + r - 1 + WSZ] - sc[i0 + r - 1];
      so[i0 + r] = s;
    }
  }
  __syncthreads();
  for (int i = tid; i < NOUT; i += TPB)
    out[(size_t)b * NOUT + i] = so[i];
}

// ---------------- launch -------------------------------------------------------
extern "C" void kernel_launch(void* const* d_in, const int* in_sizes, int n_in,
                              void* d_out, int out_size) {
  const float* x = (const float*)d_in[0];
  int B = in_sizes[0] / (2 * NFFT);
  if (B > MAXB) B = MAXB;
  if (B <= 0) return;

  kern_init_tw<<<1, 256>>>();
  kern_fft_input<<<B * 2, TPB>>>(x);
  kern_scale<<<dim3(NS, B), TPB>>>();
  kern_coh<<<dim3(NFFT / (TPB / 2), B), TPB>>>();
  kern_slide<<<B, TPB>>>((float*)d_out);
}